// round 15
// baseline (speedup 1.0000x reference)
#include <cuda_runtime.h>
#include <cuda_bf16.h>

// TemporalLightGCNLayer — padded-slot pull reduction, fp32 gather, 2 kernels.
//
//   k_scatter: p = atomicAdd(cnt[dst[e]],1);
//              slot[dst[e]*64 + p] = (src[e]<<9, w_e)   [row BYTE offset!]
//              w_e = norm[e] * exp(-(relu(lam)+1e-4) * dt[e])
//   k_reduce:  warp per node, lane = float4 chunk of the 128-wide row.
//              Slots consumed as uint4 PAIRS (2 edges / uniform load).
//              Gather address = h_lane_ptr + sl.x (pre-scaled; no IMADs).
//              fp32 FMA accumulate, one STG.128 per lane, then self-clean
//              cnt[node]=0 (g_cnt zero at module load -> every call sees
//              cnt==0 at entry; deterministic across graph replays).
//
// STRIDE=64 slots/node: degrees ~Poisson(12); P(any deg >= 64) << 1e-10;
// clamped defensively regardless.

#define D4      32            // 128 floats = 32 float4
#define N_MAX   50048
#define STRIDE  64
#define LOG2_STRIDE 6

__device__ int   g_cnt[N_MAX];
__device__ uint2 g_slot[(size_t)N_MAX * STRIDE];   // (row byte off, w-bits)

// ---- scatter: ticket into padded per-node slots ---------------------------
__global__ void __launch_bounds__(256)
k_scatter(const int* __restrict__ src,
          const int* __restrict__ dst,
          const float* __restrict__ dt,
          const float* __restrict__ norm,
          const float* __restrict__ decay_lam,
          int n_edges)
{
    int e = blockIdx.x * blockDim.x + threadIdx.x;
    if (e >= n_edges) return;

    const float lam = fmaxf(decay_lam[0], 0.0f) + 1e-4f;
    const float w   = norm[e] * __expf(-lam * dt[e]);
    const unsigned row_off = (unsigned)src[e] << 9;   // src * 128 floats * 4B
    const int d = dst[e];

    int p = atomicAdd(&g_cnt[d], 1);
    if (p < STRIDE)
        g_slot[((size_t)d << LOG2_STRIDE) + p] = make_uint2(row_off, __float_as_uint(w));
}

// ---- reduce: warp per node, paired uniform slot loads, add-only addressing -
__global__ void __launch_bounds__(128)
k_reduce(const char* __restrict__ hbytes, float4* __restrict__ out, int n_nodes)
{
    const int node = (blockIdx.x * blockDim.x + threadIdx.x) >> 5;
    const int lane = threadIdx.x & 31;
    if (node >= n_nodes) return;

    int cnt = g_cnt[node];
    if (cnt > STRIDE) cnt = STRIDE;

    const char* __restrict__ hlane = hbytes + lane * 16;   // this lane's chunk
    const uint2* __restrict__ sp   = &g_slot[(size_t)node << LOG2_STRIDE];

    float4 acc = make_float4(0.f, 0.f, 0.f, 0.f);

    const int pairs = cnt >> 1;
    #pragma unroll 4
    for (int j = 0; j < pairs; j++) {
        // 2 edges per uniform broadcast load (16B-aligned: base is 512B-aligned)
        const uint4 sl = __ldg(reinterpret_cast<const uint4*>(sp) + j);
        const float w0 = __uint_as_float(sl.y);
        const float w1 = __uint_as_float(sl.w);
        const float4 v0 = __ldg(reinterpret_cast<const float4*>(hlane + sl.x));
        const float4 v1 = __ldg(reinterpret_cast<const float4*>(hlane + sl.z));
        acc.x = fmaf(w0, v0.x, acc.x);  acc.x = fmaf(w1, v1.x, acc.x);
        acc.y = fmaf(w0, v0.y, acc.y);  acc.y = fmaf(w1, v1.y, acc.y);
        acc.z = fmaf(w0, v0.z, acc.z);  acc.z = fmaf(w1, v1.z, acc.z);
        acc.w = fmaf(w0, v0.w, acc.w);  acc.w = fmaf(w1, v1.w, acc.w);
    }
    if (cnt & 1) {
        const uint2 sl = __ldg(&sp[cnt - 1]);
        const float w  = __uint_as_float(sl.y);
        const float4 v = __ldg(reinterpret_cast<const float4*>(hlane + sl.x));
        acc.x = fmaf(w, v.x, acc.x);
        acc.y = fmaf(w, v.y, acc.y);
        acc.z = fmaf(w, v.z, acc.z);
        acc.w = fmaf(w, v.w, acc.w);
    }

    out[(size_t)node * D4 + lane] = acc;

    // self-clean AFTER the hot loop: restore cnt==0 for the next call
    if (lane == 0) g_cnt[node] = 0;
}

extern "C" void kernel_launch(void* const* d_in, const int* in_sizes, int n_in,
                              void* d_out, int out_size)
{
    const float* h         = (const float*)d_in[0];   // [N, 128]
    const int*   src       = (const int*)  d_in[1];   // [E]
    const int*   dst       = (const int*)  d_in[2];   // [E]
    const float* dt        = (const float*)d_in[3];   // [E]
    const float* norm      = (const float*)d_in[4];   // [E]
    const float* decay_lam = (const float*)d_in[5];   // [1]

    const int n_edges = in_sizes[1];
    const int n_nodes = out_size / 128;

    const int T = 256;
    k_scatter<<<(n_edges + T - 1) / T, T>>>(src, dst, dt, norm, decay_lam, n_edges);

    const int TR = 128;
    const int warps_per_blk = TR / 32;
    const int nb_reduce = (n_nodes + warps_per_blk - 1) / warps_per_blk;
    k_reduce<<<nb_reduce, TR>>>((const char*)h, (float4*)d_out, n_nodes);
}

// round 16
// speedup vs baseline: 1.0536x; 1.0536x over previous
#include <cuda_runtime.h>
#include <cuda_bf16.h>

// TemporalLightGCNLayer — padded-slot pull reduction, fp32 gather, 2 kernels.
// Reduce loop = measured-best R12 structure (uint2 slot loads, unroll 8,
// 128-thread blocks, 32 regs, ~80% occ) with ONE change: slots carry a
// pre-scaled row BYTE offset (src<<9), so the gather address is a single add
// (hlane + sl.x) instead of an IMAD.WIDE chain. Scatter is vectorized 4
// edges/thread (int4/float4 loads); one atomic per edge as before.
//
//   k_scatter: p = atomicAdd(cnt[dst[e]],1);
//              slot[dst[e]*64 + p] = (src[e]<<9, w_e),
//              w_e = norm[e] * exp(-(relu(lam)+1e-4) * dt[e])
//   k_reduce:  warp per node, lane = float4 chunk; warp-uniform slot load,
//              add-only gather address, fp32 FMA, one STG.128 per lane;
//              self-clean cnt[node]=0 AFTER the loop (g_cnt zero at module
//              load -> every call sees cnt==0 at entry; deterministic).
//
// STRIDE=64 slots/node: degrees ~Poisson(12); P(any deg >= 64) << 1e-10;
// clamped defensively regardless.

#define D4      32            // 128 floats = 32 float4
#define N_MAX   50048
#define STRIDE  64
#define LOG2_STRIDE 6

__device__ int   g_cnt[N_MAX];
__device__ uint2 g_slot[(size_t)N_MAX * STRIDE];   // (row byte off, w-bits)

// ---- scatter: 4 edges/thread, ticket into padded per-node slots -----------
__global__ void __launch_bounds__(256)
k_scatter(const int4* __restrict__ src4,
          const int4* __restrict__ dst4,
          const float4* __restrict__ dt4,
          const float4* __restrict__ norm4,
          const float* __restrict__ decay_lam,
          int n_edges)
{
    const int q = blockIdx.x * blockDim.x + threadIdx.x;   // quad index
    const int e0 = q << 2;
    if (e0 >= n_edges) return;

    const float lam = fmaxf(decay_lam[0], 0.0f) + 1e-4f;

    const int4   s4 = __ldg(&src4[q]);
    const int4   d4 = __ldg(&dst4[q]);
    const float4 t4 = __ldg(&dt4[q]);
    const float4 n4 = __ldg(&norm4[q]);

    const int rem = n_edges - e0;   // >=1 here

    #define PUT(K, SS, DD, TT, NN)                                            \
        if (K < rem) {                                                        \
            const float w = (NN) * __expf(-lam * (TT));                       \
            int p = atomicAdd(&g_cnt[(DD)], 1);                               \
            if (p < STRIDE)                                                   \
                g_slot[((size_t)(DD) << LOG2_STRIDE) + p] =                   \
                    make_uint2((unsigned)(SS) << 9, __float_as_uint(w));      \
        }
    PUT(0, s4.x, d4.x, t4.x, n4.x)
    PUT(1, s4.y, d4.y, t4.y, n4.y)
    PUT(2, s4.z, d4.z, t4.z, n4.z)
    PUT(3, s4.w, d4.w, t4.w, n4.w)
    #undef PUT
}

// ---- reduce: warp per node, uniform slot loads, add-only addressing -------
__global__ void __launch_bounds__(128)
k_reduce(const char* __restrict__ hbytes, float4* __restrict__ out, int n_nodes)
{
    const int node = (blockIdx.x * blockDim.x + threadIdx.x) >> 5;
    const int lane = threadIdx.x & 31;
    if (node >= n_nodes) return;

    int cnt = g_cnt[node];
    if (cnt > STRIDE) cnt = STRIDE;

    const char* __restrict__ hlane = hbytes + lane * 16;   // this lane's chunk
    const uint2* __restrict__ sp   = &g_slot[(size_t)node << LOG2_STRIDE];

    float4 acc = make_float4(0.f, 0.f, 0.f, 0.f);

    #pragma unroll 8
    for (int j = 0; j < cnt; j++) {
        const uint2 sl = __ldg(&sp[j]);        // warp-uniform broadcast load
        const float w  = __uint_as_float(sl.y);
        const float4 v = __ldg(reinterpret_cast<const float4*>(hlane + sl.x));
        acc.x = fmaf(w, v.x, acc.x);
        acc.y = fmaf(w, v.y, acc.y);
        acc.z = fmaf(w, v.z, acc.z);
        acc.w = fmaf(w, v.w, acc.w);
    }
    out[(size_t)node * D4 + lane] = acc;

    // self-clean AFTER the hot loop: restore cnt==0 for the next call
    if (lane == 0) g_cnt[node] = 0;
}

extern "C" void kernel_launch(void* const* d_in, const int* in_sizes, int n_in,
                              void* d_out, int out_size)
{
    const float* h         = (const float*)d_in[0];   // [N, 128]
    const int*   src       = (const int*)  d_in[1];   // [E]
    const int*   dst       = (const int*)  d_in[2];   // [E]
    const float* dt        = (const float*)d_in[3];   // [E]
    const float* norm      = (const float*)d_in[4];   // [E]
    const float* decay_lam = (const float*)d_in[5];   // [1]

    const int n_edges = in_sizes[1];
    const int n_nodes = out_size / 128;

    const int T = 256;
    const int quads = (n_edges + 3) / 4;
    k_scatter<<<(quads + T - 1) / T, T>>>(
        (const int4*)src, (const int4*)dst, (const float4*)dt,
        (const float4*)norm, decay_lam, n_edges);

    const int TR = 128;
    const int warps_per_blk = TR / 32;
    const int nb_reduce = (n_nodes + warps_per_blk - 1) / warps_per_blk;
    k_reduce<<<nb_reduce, TR>>>((const char*)h, (float4*)d_out, n_nodes);
}